// round 1
// baseline (speedup 1.0000x reference)
#include <cuda_runtime.h>

// MPS contraction, fused segment-product approach.
// N=1024 sites, B=256, D=16, d=2, C=10.

#define N_SITES 1024
#define B_DIM   256
#define D_DIM   16
#define C_DIM   10
#define SEG     32
#define NSEG    (N_SITES / SEG)   // 32
#define BG      16                // batches per block in kernel 1
#define THREADS 256

// Scratch: per-(b, segment) 16x16 product. 256*32*256 floats = 8 MB.
__device__ float g_segprod[(size_t)B_DIM * NSEG * D_DIM * D_DIM];

// ---------------------------------------------------------------------------
// Kernel 1: per-segment matrix products.
// grid = (NSEG, B/BG); block = 256 threads.
// Thread (bl = tid>>4, i = tid&15) owns row i of batch (b0+bl)'s running product.
// ---------------------------------------------------------------------------
__global__ __launch_bounds__(THREADS)
void seg_kernel(const float* __restrict__ x, const float* __restrict__ tensor)
{
    extern __shared__ float sm[];
    float* Tsh = sm;                               // [SEG][2][16][17] = 17408 floats
    float* Ash = sm + SEG * 2 * 16 * 17;           // [2][BG][264]     = 8448 floats
    float* xsh = Ash + 2 * BG * 264;               // [SEG][BG][2]     = 1024 floats

    const int seg = blockIdx.x;
    const int b0  = blockIdx.y * BG;
    const int tid = threadIdx.x;
    const int bl  = tid >> 4;
    const int i   = tid & 15;

    // Load tensor chunk for this segment: SEG sites * 512 floats, coalesced.
    // tensor layout: [n][l][r][dd], dd fastest.
    const float* tbase = tensor + (size_t)seg * SEG * 512;
    for (int idx = tid; idx < SEG * 512; idx += THREADS) {
        int s   = idx >> 9;
        int rem = idx & 511;
        int l   = rem >> 5;
        int r   = (rem >> 1) & 15;
        int dd  = rem & 1;
        Tsh[((s * 2 + dd) * 16 + l) * 17 + r] = tbase[idx];
    }
    // Load x chunk: x layout [n][b][dd].
    for (int idx = tid; idx < SEG * BG * 2; idx += THREADS) {
        int s   = idx / (BG * 2);
        int rem = idx - s * (BG * 2);
        int blx = rem >> 1;
        int dd  = rem & 1;
        xsh[(s * BG + blx) * 2 + dd] =
            x[((size_t)(seg * SEG + s)) * (B_DIM * 2) + (b0 + blx) * 2 + dd];
    }
    __syncthreads();

    // Running product row (row i of batch bl's product), init to identity row.
    float P[16];
#pragma unroll
    for (int k = 0; k < 16; k++) P[k] = (k == i) ? 1.0f : 0.0f;

    for (int s = 0; s < SEG; s++) {
        float* Abuf = Ash + ((s & 1) * BG + bl) * 264;

        // Form row i of A = x0*T0 + x1*T1 for my batch into shared.
        const float x0 = xsh[(s * BG + bl) * 2 + 0];
        const float x1 = xsh[(s * BG + bl) * 2 + 1];
        const float* t0 = &Tsh[((s * 2 + 0) * 16 + i) * 17];
        const float* t1 = &Tsh[((s * 2 + 1) * 16 + i) * 17];
        float arow[16];
#pragma unroll
        for (int j = 0; j < 16; j++)
            arow[j] = fmaf(x0, t0[j], 0.0f) + x1 * t1[j];
        {
            float4* d4 = (float4*)(Abuf + i * 16);
            d4[0] = make_float4(arow[0],  arow[1],  arow[2],  arow[3]);
            d4[1] = make_float4(arow[4],  arow[5],  arow[6],  arow[7]);
            d4[2] = make_float4(arow[8],  arow[9],  arow[10], arow[11]);
            d4[3] = make_float4(arow[12], arow[13], arow[14], arow[15]);
        }
        // Each batch's A is produced and consumed by the same half-warp:
        // warp-level sync suffices (no block barrier in the hot loop).
        __syncwarp();

        // P_row = P_row * A   (16 broadcast LDS.128 rows + 256 FMA)
        float np_[16];
#pragma unroll
        for (int j = 0; j < 16; j++) np_[j] = 0.0f;
#pragma unroll
        for (int k = 0; k < 16; k++) {
            const float pk = P[k];
            const float4 a0 = *(const float4*)(Abuf + k * 16 + 0);
            const float4 a1 = *(const float4*)(Abuf + k * 16 + 4);
            const float4 a2 = *(const float4*)(Abuf + k * 16 + 8);
            const float4 a3 = *(const float4*)(Abuf + k * 16 + 12);
            np_[0]  = fmaf(pk, a0.x, np_[0]);
            np_[1]  = fmaf(pk, a0.y, np_[1]);
            np_[2]  = fmaf(pk, a0.z, np_[2]);
            np_[3]  = fmaf(pk, a0.w, np_[3]);
            np_[4]  = fmaf(pk, a1.x, np_[4]);
            np_[5]  = fmaf(pk, a1.y, np_[5]);
            np_[6]  = fmaf(pk, a1.z, np_[6]);
            np_[7]  = fmaf(pk, a1.w, np_[7]);
            np_[8]  = fmaf(pk, a2.x, np_[8]);
            np_[9]  = fmaf(pk, a2.y, np_[9]);
            np_[10] = fmaf(pk, a2.z, np_[10]);
            np_[11] = fmaf(pk, a2.w, np_[11]);
            np_[12] = fmaf(pk, a3.x, np_[12]);
            np_[13] = fmaf(pk, a3.y, np_[13]);
            np_[14] = fmaf(pk, a3.z, np_[14]);
            np_[15] = fmaf(pk, a3.w, np_[15]);
        }
#pragma unroll
        for (int j = 0; j < 16; j++) P[j] = np_[j];
    }

    // Store segment product row.
    float* op = g_segprod + ((((size_t)(b0 + bl)) * NSEG + seg) << 8) + i * 16;
    float4* op4 = (float4*)op;
    op4[0] = make_float4(P[0],  P[1],  P[2],  P[3]);
    op4[1] = make_float4(P[4],  P[5],  P[6],  P[7]);
    op4[2] = make_float4(P[8],  P[9],  P[10], P[11]);
    op4[3] = make_float4(P[12], P[13], P[14], P[15]);
}

// ---------------------------------------------------------------------------
// Kernel 2: combine segment products into boundary vectors + final output.
// One warp per batch b. Lanes 0-15: left chain v = e0^T * S0 * ... * S15.
// Lanes 16-31: right chain w = S16 * ... * S31 * e0  (applied right-to-left).
// Then out[b][o] = sum_{l,r} v[l] * Aout[o][l][r] * w[r].
// grid = 32 blocks x 256 threads (8 warps/block).
// ---------------------------------------------------------------------------
__global__ __launch_bounds__(256)
void combine_kernel(const float* __restrict__ Aout, float* __restrict__ out)
{
    const int wib  = threadIdx.x >> 5;                 // warp in block
    const int b    = blockIdx.x * 8 + wib;             // batch
    const int lane = threadIdx.x & 31;
    const int grp  = lane >> 4;                        // 0 = left, 1 = right
    const int j    = lane & 15;

    float v = (j == 0) ? 1.0f : 0.0f;

    for (int t = 0; t < 16; t++) {
        const int seg = (grp == 0) ? t : (31 - t);
        const float* S = g_segprod + (((size_t)b * NSEG + seg) << 8);
        float col[16];
        if (grp == 0) {
            // left: v'_j = sum_k v[k] * S[k][j]  -> need column j
#pragma unroll
            for (int k = 0; k < 16; k++) col[k] = S[k * 16 + j];
        } else {
            // right: w'_j = sum_k S[j][k] * w[k] -> need row j
#pragma unroll
            for (int k = 0; k < 16; k++) col[k] = S[j * 16 + k];
        }
        float acc = 0.0f;
#pragma unroll
        for (int k = 0; k < 16; k++) {
            float vk = __shfl_sync(0xffffffffu, v, (grp << 4) + k);
            acc = fmaf(vk, col[k], acc);
        }
        v = acc;
    }

    // Share v (lanes 0-15 = Al) and w (lanes 16-31 = Ar) within the warp.
    __shared__ float vw[8][32];
    vw[wib][lane] = v;
    __syncwarp();

    if (lane < C_DIM) {
        const float* Ao = Aout + lane * 256;   // Aout[o][l][r]
        float acc = 0.0f;
#pragma unroll
        for (int l = 0; l < 16; l++) {
            const float al = vw[wib][l];
#pragma unroll
            for (int r = 0; r < 16; r++)
                acc = fmaf(al * Ao[l * 16 + r], vw[wib][16 + r], acc);
        }
        out[b * C_DIM + lane] = acc;
    }
}

// ---------------------------------------------------------------------------
extern "C" void kernel_launch(void* const* d_in, const int* in_sizes, int n_in,
                              void* d_out, int out_size)
{
    const float* x      = (const float*)d_in[0];  // (N, B, d)
    const float* tensor = (const float*)d_in[1];  // (N, D, D, d)
    const float* Aout   = (const float*)d_in[2];  // (C, D, D)
    float* out = (float*)d_out;                   // (B, C)

    const int smem_bytes = (SEG * 2 * 16 * 17 + 2 * BG * 264 + SEG * BG * 2) * 4; // 107520
    cudaFuncSetAttribute(seg_kernel,
                         cudaFuncAttributeMaxDynamicSharedMemorySize, smem_bytes);

    dim3 grid1(NSEG, B_DIM / BG);   // (32, 16)
    seg_kernel<<<grid1, THREADS, smem_bytes>>>(x, tensor);

    combine_kernel<<<B_DIM / 8, 256>>>(Aout, out);
}

// round 2
// speedup vs baseline: 1.1609x; 1.1609x over previous
#include <cuda_runtime.h>

// MPS contraction via site-pair precompute + boundary-vector chains.
// N=1024 sites, B=256, D=16, d=2, C=10.
//
// Math: A_n = x[n,0]*T0_n + x[n,1]*T1_n (16x16). Need Al = e0^T * prod(A_0..511),
// Ar = prod(A_512..1023) * e0, out[b,o] = Al . Aout[o] . Ar.
// Pair p: M_{d1d2}[p] = T_{2p,d1} @ T_{2p+1,d2} (batch-independent).
// Chain step: v' = sum_{d1d2} c_{d1d2} * (v . M_{d1d2}),  c = x[2p,d1]*x[2p+1,d2].
// Right-half pairs stored transposed so the right chain is also a row-vector chain.

#define NPAIR 512
#define B_DIM 256
#define C_DIM 10

// g_M[p][e]: e = k*16+j, float4 = (M00,M01,M10,M11)[k][j]  (transposed for p>=256)
__device__ float4 g_M[NPAIR * 256];   // 2 MB
// g_C[p][b] = (x0*y0, x0*y1, x1*y0, x1*y1)
__device__ float4 g_C[NPAIR * B_DIM]; // 2 MB

// ---------------------------------------------------------------------------
// Kernel 1: per-pair matrices + coefficients. grid=512, block=256.
// ---------------------------------------------------------------------------
__global__ __launch_bounds__(256)
void pair_kernel(const float* __restrict__ tensor, const float* __restrict__ x)
{
    __shared__ float T0[512], T1[512];   // site 2p, site 2p+1: [l][r][dd]
    const int p = blockIdx.x;
    const int t = threadIdx.x;

    const float* base = tensor + (size_t)p * 1024;
    T0[t]       = base[t];
    T0[t + 256] = base[t + 256];
    T1[t]       = base[512 + t];
    T1[t + 256] = base[768 + t];
    __syncthreads();

    const int l = t >> 4;
    const int r = t & 15;
    float a00 = 0.f, a01 = 0.f, a10 = 0.f, a11 = 0.f;
#pragma unroll
    for (int k = 0; k < 16; k++) {
        const float2 a = *(const float2*)&T0[l * 32 + k * 2];   // (T0_d0, T0_d1)[l][k]
        const float2 b = *(const float2*)&T1[k * 32 + r * 2];   // (T1_d0, T1_d1)[k][r]
        a00 = fmaf(a.x, b.x, a00);
        a01 = fmaf(a.x, b.y, a01);
        a10 = fmaf(a.y, b.x, a10);
        a11 = fmaf(a.y, b.y, a11);
    }
    // left pairs: store M[l][r] at [l*16+r]; right pairs: transposed at [r*16+l]
    const int idx = (p < 256) ? (l * 16 + r) : (r * 16 + l);
    g_M[p * 256 + idx] = make_float4(a00, a01, a10, a11);

    // coefficients for batch b = t
    const float2 xa = *(const float2*)&x[(size_t)(2 * p) * 512 + t * 2];
    const float2 xb = *(const float2*)&x[(size_t)(2 * p) * 512 + 512 + t * 2];
    g_C[p * 256 + t] = make_float4(xa.x * xb.x, xa.x * xb.y, xa.y * xb.x, xa.y * xb.y);
}

// ---------------------------------------------------------------------------
// Kernel 2: chains. grid=128 blocks x 128 threads (4 warps).
// Warp w: side = w&1 (0=left,1=right), batch = blockIdx*2 + (w>>1).
// Warp = one chain: lane (j = lane&15, h = lane>>4); lane handles k in [8h,8h+8).
// Step t: left uses pair t, right uses pair 511-t (transposed storage).
// M staged in shared, double-buffered, register-prefetched.
// ---------------------------------------------------------------------------
__global__ __launch_bounds__(128)
void chain_kernel(const float* __restrict__ Aout, float* __restrict__ out)
{
    __shared__ float4 Msh[2][2][256];   // [stage][side][k*16+j], 16 KB
    __shared__ float  vsh[4][16];       // final Al/Ar per warp

    const int tid  = threadIdx.x;
    const int w    = tid >> 5;
    const int lane = tid & 31;
    const int side = w & 1;
    const int b    = blockIdx.x * 2 + (w >> 1);
    const int j    = lane & 15;
    const int h    = lane >> 4;

    // --- staging: thread tid covers flattened elements f = tid*4 .. tid*4+3
    //     f in [0,512): sd = f>>8 (side), e = f&255.
    float4 pf[4];

    // preload stage 0 (pairs: side0 -> 0, side1 -> 511)
#pragma unroll
    for (int i = 0; i < 4; i++) {
        const int f  = tid * 4 + i;
        const int sd = f >> 8;
        const int e  = f & 255;
        const int p  = sd ? 511 : 0;
        pf[i] = g_M[p * 256 + e];
    }
#pragma unroll
    for (int i = 0; i < 4; i++)
        ((float4*)Msh[0])[tid * 4 + i] = pf[i];

    float4 c_cur = g_C[(side ? 511 : 0) * 256 + b];
    float4 c_nxt;
    __syncthreads();

    // v split: this lane holds v[8h .. 8h+7]
    float vloc[8];
#pragma unroll
    for (int kk = 0; kk < 8; kk++) vloc[kk] = 0.f;
    if (h == 0) vloc[0] = 1.f;   // v = e0
    // replicate: both halves' lane j=0? only k=0 belongs to h=0 half. OK.

    float vp = 0.f;

    for (int t = 0; t < 256; t++) {
        const int st = t & 1;

        // register-prefetch next stage + next c
        if (t + 1 < 256) {
#pragma unroll
            for (int i = 0; i < 4; i++) {
                const int f  = tid * 4 + i;
                const int sd = f >> 8;
                const int e  = f & 255;
                const int p  = sd ? (510 - t) : (t + 1);
                pf[i] = g_M[p * 256 + e];
            }
            c_nxt = g_C[(side ? (510 - t) : (t + 1)) * 256 + b];
        }

        // compute: partial dots over my k-half
        const float4* Mcol = Msh[st][side];
        float a0 = 0.f, a1 = 0.f, a2 = 0.f, a3 = 0.f;
#pragma unroll
        for (int kk = 0; kk < 8; kk++) {
            const float4 m = Mcol[(h * 8 + kk) * 16 + j];
            const float vk = vloc[kk];
            a0 = fmaf(vk, m.x, a0);
            a1 = fmaf(vk, m.y, a1);
            a2 = fmaf(vk, m.z, a2);
            a3 = fmaf(vk, m.w, a3);
        }
        // cross-half reduction (lane j,0 <-> lane j,1)
        a0 += __shfl_xor_sync(0xffffffffu, a0, 16);
        a1 += __shfl_xor_sync(0xffffffffu, a1, 16);
        a2 += __shfl_xor_sync(0xffffffffu, a2, 16);
        a3 += __shfl_xor_sync(0xffffffffu, a3, 16);

        // combine with coefficients -> new v_j (both halves compute it)
        vp = fmaf(c_cur.x, a0, fmaf(c_cur.y, a1, fmaf(c_cur.z, a2, c_cur.w * a3)));

        // broadcast my half of new v: need v[h*8+kk], held by lane (lane&16)+(h*8+kk)
        const int srcbase = (lane & 16) + h * 8;
#pragma unroll
        for (int kk = 0; kk < 8; kk++)
            vloc[kk] = __shfl_sync(0xffffffffu, vp, srcbase + kk);

        // store next stage
        if (t + 1 < 256) {
#pragma unroll
            for (int i = 0; i < 4; i++)
                ((float4*)Msh[st ^ 1])[tid * 4 + i] = pf[i];
            c_cur = c_nxt;
        }
        __syncthreads();
    }

    // final vector for this chain: vp (column j), identical in both halves
    if (h == 0) vsh[w][j] = vp;
    __syncthreads();

    // epilogue: out[b,o] = sum_{l,r} Al[l] * Aout[o][l][r] * Ar[r]
    if (tid < 2 * C_DIM) {
        const int bl = tid / C_DIM;           // local batch
        const int o  = tid % C_DIM;
        const float* Al = vsh[bl * 2 + 0];
        const float* Ar = vsh[bl * 2 + 1];
        const float4* Ao = (const float4*)(Aout + o * 256);
        float acc = 0.f;
#pragma unroll
        for (int l = 0; l < 16; l++) {
            const float al = Al[l];
#pragma unroll
            for (int rq = 0; rq < 4; rq++) {
                const float4 a = Ao[l * 4 + rq];
                acc = fmaf(al * a.x, Ar[rq * 4 + 0], acc);
                acc = fmaf(al * a.y, Ar[rq * 4 + 1], acc);
                acc = fmaf(al * a.z, Ar[rq * 4 + 2], acc);
                acc = fmaf(al * a.w, Ar[rq * 4 + 3], acc);
            }
        }
        out[(blockIdx.x * 2 + bl) * C_DIM + o] = acc;
    }
}

// ---------------------------------------------------------------------------
extern "C" void kernel_launch(void* const* d_in, const int* in_sizes, int n_in,
                              void* d_out, int out_size)
{
    const float* x      = (const float*)d_in[0];  // (N, B, d)
    const float* tensor = (const float*)d_in[1];  // (N, D, D, d)
    const float* Aout   = (const float*)d_in[2];  // (C, D, D)
    float* out = (float*)d_out;                   // (B, C)

    pair_kernel<<<NPAIR, 256>>>(tensor, x);
    chain_kernel<<<B_DIM / 2, 128>>>(Aout, out);
}

// round 3
// speedup vs baseline: 1.9187x; 1.6527x over previous
#include <cuda_runtime.h>

// MPS contraction: pairs -> batch-independent quad-combos (R) ->
// per-batch quad matrices (Q) -> register-resident boundary-vector chains.
// N=1024 sites, B=256, D=16, d=2, C=10.

#define NPAIR 512
#define NQUAD 256          // quads 0..127 left, 128..255 right (stored transposed)
#define B_DIM 256
#define C_DIM 10

// g_M[p][k*16+j] = float4(M00,M01,M10,M11)[k][j]; transposed storage for p>=256.
__device__ float4 g_M[NPAIR * 256];            // 2 MB
// g_C[p*256+b] = (x0y0, x0y1, x1y0, x1y1) with x=x[2p,b,:], y=x[2p+1,b,:]
__device__ float4 g_C[NPAIR * B_DIM];          // 2 MB
// g_R[q*4096 + g*256 + k*16 + j] = R_g[k][j], g = e*4+f (batch-independent)
__device__ float g_R[NQUAD * 16 * 256];        // 4 MB
// g_Q[((b*256+q)*16 + j)*16 + k] = Qd[b][q][k][j]  (column-major per (b,q))
__device__ float g_Q[(size_t)B_DIM * NQUAD * 256]; // 64 MB

// ---------------------------------------------------------------------------
// K1: pair matrices (batch-independent) + coefficients. grid=512, block=256.
// ---------------------------------------------------------------------------
__global__ __launch_bounds__(256)
void pair_kernel(const float* __restrict__ tensor, const float* __restrict__ x)
{
    __shared__ float T0[512], T1[512];   // [l][r][dd]
    const int p = blockIdx.x;
    const int t = threadIdx.x;

    const float* base = tensor + (size_t)p * 1024;
    T0[t]       = base[t];
    T0[t + 256] = base[t + 256];
    T1[t]       = base[512 + t];
    T1[t + 256] = base[768 + t];
    __syncthreads();

    const int l = t >> 4;
    const int r = t & 15;
    float a00 = 0.f, a01 = 0.f, a10 = 0.f, a11 = 0.f;
#pragma unroll
    for (int k = 0; k < 16; k++) {
        const float2 a = *(const float2*)&T0[l * 32 + k * 2];
        const float2 b = *(const float2*)&T1[k * 32 + r * 2];
        a00 = fmaf(a.x, b.x, a00);
        a01 = fmaf(a.x, b.y, a01);
        a10 = fmaf(a.y, b.x, a10);
        a11 = fmaf(a.y, b.y, a11);
    }
    const int idx = (p < 256) ? (l * 16 + r) : (r * 16 + l);   // transpose right side
    g_M[p * 256 + idx] = make_float4(a00, a01, a10, a11);

    const float2 xa = *(const float2*)&x[(size_t)(2 * p) * 512 + t * 2];
    const float2 xb = *(const float2*)&x[(size_t)(2 * p) * 512 + 512 + t * 2];
    g_C[p * 256 + t] = make_float4(xa.x * xb.x, xa.x * xb.y, xa.y * xb.x, xa.y * xb.y);
}

// ---------------------------------------------------------------------------
// K2: R_g[q] for all 16 combos. grid=256 (one per quad), block=256.
// Left (q<128):  R_{e*4+f} = S_{2q,e}   @ S_{2q+1,f}
// Right(q>=128): R_{e*4+f} = S_{2q+1,f} @ S_{2q,e}   (gives transposed quad)
// ---------------------------------------------------------------------------
__global__ __launch_bounds__(256)
void r_kernel()
{
    __shared__ float SA[4][16 * 17], SB[4][16 * 17];   // padded rows (bank spread)
    const int q = blockIdx.x;
    const int t = threadIdx.x;
    const int pA = 2 * q, pB = 2 * q + 1;

    {
        const float4 fa = g_M[pA * 256 + t];
        const float4 fb = g_M[pB * 256 + t];
        const int k = t >> 4, j = t & 15;
        SA[0][k * 17 + j] = fa.x; SA[1][k * 17 + j] = fa.y;
        SA[2][k * 17 + j] = fa.z; SA[3][k * 17 + j] = fa.w;
        SB[0][k * 17 + j] = fb.x; SB[1][k * 17 + j] = fb.y;
        SB[2][k * 17 + j] = fb.z; SB[3][k * 17 + j] = fb.w;
    }
    __syncthreads();

    const int g  = t >> 4;     // combo e*4+f
    const int kk = t & 15;     // output row
    const int e = g >> 2, f = g & 3;
    const float* P1 = (q < 128) ? SA[e] : SB[f];   // first operand
    const float* P2 = (q < 128) ? SB[f] : SA[e];   // second operand

    float acc[16];
#pragma unroll
    for (int j = 0; j < 16; j++) acc[j] = 0.f;
#pragma unroll
    for (int m = 0; m < 16; m++) {
        const float a = P1[kk * 17 + m];
#pragma unroll
        for (int j = 0; j < 16; j++)
            acc[j] = fmaf(a, P2[m * 17 + j], acc[j]);
    }
    float4* dst = (float4*)&g_R[q * 4096 + g * 256 + kk * 16];
    dst[0] = make_float4(acc[0],  acc[1],  acc[2],  acc[3]);
    dst[1] = make_float4(acc[4],  acc[5],  acc[6],  acc[7]);
    dst[2] = make_float4(acc[8],  acc[9],  acc[10], acc[11]);
    dst[3] = make_float4(acc[12], acc[13], acc[14], acc[15]);
}

// ---------------------------------------------------------------------------
// K3: per-batch quad matrices. Qd[b][q] = sum_g (cA_e * cB_f) R_g[q].
// grid = (4 batch-quarters, 256 quads), block = 256 = (16 bgroups x 16 cols).
// Thread (bg, j) handles 4 batches, computes column j (16 k-values) each.
// ---------------------------------------------------------------------------
__global__ __launch_bounds__(256, 2)
void q_kernel()
{
    __shared__ float Rsh[4096];    // 16 KB, same layout as g_R slice
    const int q  = blockIdx.y;
    const int t  = threadIdx.x;

    {   // stage R for this quad: 16 floats (4 x float4) per thread, coalesced
        const float4* src = (const float4*)&g_R[q * 4096 + t * 16];
        float4* dst = (float4*)&Rsh[t * 16];
        dst[0] = src[0]; dst[1] = src[1]; dst[2] = src[2]; dst[3] = src[3];
    }
    __syncthreads();

    const int bg = t >> 4;
    const int j  = t & 15;
    const int b0 = blockIdx.x * 64 + bg * 4;

    float cA[4][4], cB[4][4];
#pragma unroll
    for (int bb = 0; bb < 4; bb++) {
        const float4 a = g_C[(2 * q) * 256 + b0 + bb];
        const float4 c = g_C[(2 * q + 1) * 256 + b0 + bb];
        cA[bb][0] = a.x; cA[bb][1] = a.y; cA[bb][2] = a.z; cA[bb][3] = a.w;
        cB[bb][0] = c.x; cB[bb][1] = c.y; cB[bb][2] = c.z; cB[bb][3] = c.w;
    }

    float acc[4][16];
#pragma unroll
    for (int bb = 0; bb < 4; bb++)
#pragma unroll
        for (int k = 0; k < 16; k++) acc[bb][k] = 0.f;

#pragma unroll
    for (int e = 0; e < 4; e++) {
#pragma unroll
        for (int f = 0; f < 4; f++) {
            const float c0 = cA[0][e] * cB[0][f];
            const float c1 = cA[1][e] * cB[1][f];
            const float c2 = cA[2][e] * cB[2][f];
            const float c3 = cA[3][e] * cB[3][f];
            const float* Rb = &Rsh[(e * 4 + f) * 256 + j];
#pragma unroll
            for (int k = 0; k < 16; k++) {
                const float r = Rb[k * 16];       // conflict-free scalar LDS
                acc[0][k] = fmaf(c0, r, acc[0][k]);
                acc[1][k] = fmaf(c1, r, acc[1][k]);
                acc[2][k] = fmaf(c2, r, acc[2][k]);
                acc[3][k] = fmaf(c3, r, acc[3][k]);
            }
        }
    }

#pragma unroll
    for (int bb = 0; bb < 4; bb++) {
        float4* dst = (float4*)&g_Q[(((size_t)(b0 + bb) * 256 + q) * 16 + j) * 16];
        dst[0] = make_float4(acc[bb][0],  acc[bb][1],  acc[bb][2],  acc[bb][3]);
        dst[1] = make_float4(acc[bb][4],  acc[bb][5],  acc[bb][6],  acc[bb][7]);
        dst[2] = make_float4(acc[bb][8],  acc[bb][9],  acc[bb][10], acc[bb][11]);
        dst[3] = make_float4(acc[bb][12], acc[bb][13], acc[bb][14], acc[bb][15]);
    }
}

// ---------------------------------------------------------------------------
// K4: chains, fully register-resident, no shared, no block sync.
// grid=128 x 64 threads (2 warps). Warp = one batch; lanes 0-15 left chain
// (q = t ascending), lanes 16-31 right chain (q = 255-t, transposed storage).
// Lane j: vp_j = sum_k v[k] * Qcol[j][k]; v re-broadcast by 16 shfls.
// ---------------------------------------------------------------------------
__global__ __launch_bounds__(64)
void chain_kernel(const float* __restrict__ Aout, float* __restrict__ out)
{
    const int tid  = threadIdx.x;
    const int w    = tid >> 5;
    const int lane = tid & 31;
    const int b    = blockIdx.x * 2 + w;
    const int h    = lane >> 4;
    const int j    = lane & 15;

    // column base: g_Q index = b*65536 + q*256 + j*16 + k
    const float4* base = (const float4*)(g_Q + (size_t)b * 65536 + j * 16);
    // as float4: offset q*64 + kq

    float4 buf0[4], buf1[4];
    {
        const int q0 = h ? 255 : 0;
        const int q1 = h ? 254 : 1;
#pragma unroll
        for (int kq = 0; kq < 4; kq++) buf0[kq] = base[q0 * 64 + kq];
#pragma unroll
        for (int kq = 0; kq < 4; kq++) buf1[kq] = base[q1 * 64 + kq];
    }

    float v[16];
#pragma unroll
    for (int k = 0; k < 16; k++) v[k] = (k == 0) ? 1.f : 0.f;
    float vp = 0.f;

#pragma unroll 2
    for (int t = 0; t < 128; t++) {
        float4* cur = (t & 1) ? buf1 : buf0;

        float a0 = 0.f, a1 = 0.f;
        a0 = fmaf(v[0],  cur[0].x, a0);  a1 = fmaf(v[1],  cur[0].y, a1);
        a0 = fmaf(v[2],  cur[0].z, a0);  a1 = fmaf(v[3],  cur[0].w, a1);
        a0 = fmaf(v[4],  cur[1].x, a0);  a1 = fmaf(v[5],  cur[1].y, a1);
        a0 = fmaf(v[6],  cur[1].z, a0);  a1 = fmaf(v[7],  cur[1].w, a1);
        a0 = fmaf(v[8],  cur[2].x, a0);  a1 = fmaf(v[9],  cur[2].y, a1);
        a0 = fmaf(v[10], cur[2].z, a0);  a1 = fmaf(v[11], cur[2].w, a1);
        a0 = fmaf(v[12], cur[3].x, a0);  a1 = fmaf(v[13], cur[3].y, a1);
        a0 = fmaf(v[14], cur[3].z, a0);  a1 = fmaf(v[15], cur[3].w, a1);

        // prefetch step t+2 into the buffer just consumed
        if (t + 2 < 128) {
            const int qn = h ? (253 - t) : (t + 2);
#pragma unroll
            for (int kq = 0; kq < 4; kq++) cur[kq] = base[qn * 64 + kq];
        }

        vp = a0 + a1;
        const int src = (lane & 16);
#pragma unroll
        for (int k = 0; k < 16; k++)
            v[k] = __shfl_sync(0xffffffffu, vp, src | k);
    }

    // Epilogue: Al_k in lane k's vp, Ar_k in lane (16+k)'s vp.
    float ar[16];
#pragma unroll
    for (int k = 0; k < 16; k++)
        ar[k] = __shfl_sync(0xffffffffu, vp, 16 + k);
    float al[16];
#pragma unroll
    for (int k = 0; k < 16; k++)
        al[k] = __shfl_sync(0xffffffffu, vp, k);

    if (lane < C_DIM) {
        const float4* Ao = (const float4*)(Aout + lane * 256);
        float acc = 0.f;
#pragma unroll
        for (int l = 0; l < 16; l++) {
            const float a = al[l];
#pragma unroll
            for (int rq = 0; rq < 4; rq++) {
                const float4 x = Ao[l * 4 + rq];
                acc = fmaf(a * x.x, ar[rq * 4 + 0], acc);
                acc = fmaf(a * x.y, ar[rq * 4 + 1], acc);
                acc = fmaf(a * x.z, ar[rq * 4 + 2], acc);
                acc = fmaf(a * x.w, ar[rq * 4 + 3], acc);
            }
        }
        out[b * C_DIM + lane] = acc;
    }
}

// ---------------------------------------------------------------------------
extern "C" void kernel_launch(void* const* d_in, const int* in_sizes, int n_in,
                              void* d_out, int out_size)
{
    const float* x      = (const float*)d_in[0];  // (N, B, d)
    const float* tensor = (const float*)d_in[1];  // (N, D, D, d)
    const float* Aout   = (const float*)d_in[2];  // (C, D, D)
    float* out = (float*)d_out;                   // (B, C)

    pair_kernel<<<NPAIR, 256>>>(tensor, x);
    r_kernel<<<NQUAD, 256>>>();
    q_kernel<<<dim3(4, NQUAD), 256>>>();
    chain_kernel<<<B_DIM / 2, 64>>>(Aout, out);
}